// round 16
// baseline (speedup 1.0000x reference)
#include <cuda_runtime.h>

// AllZeroDigitalFilter: time-varying FIR, 50 taps, frame period 80.
// y[b,t] = sum_{j=0..49} x[b, t+j-49] * h[b,t,j]
// h[t=n*80+p][j] = (1-p/80)*bf[n][j] + (p/80)*bf[min(n+1,N-1)][j], bf[n][j]=b[n][49-j]
// Split: y = a0 + w*a1, a0 = sum x*cL, a1 = sum x*(cR-cL).
// (a0,a1) packed in a 64-bit pair, advanced with fma.rn.f32x2 (FFMA2).
// Taps in PAIRS: one LDS.128 = 2 taps' (cL,cD) [16B-aligned, warp-broadcast].
// x stored DUPLICATED (v,v): refill = 2 LDS.64, zero pack MOVs in mainloop.
// KOUT=5 -> per-thread float2 stride 5 (odd) -> conflict-free banks.
// 6-slot named-register circular window, advanced 2/pair (period-3 phases).

#define TAPS     50
#define FP       80
#define FPB      10            // frames per block
#define THREADS  160           // 16 threads/frame, exactly 5 warps
#define KOUT     5             // outputs per thread (16*5 = 80 = FP)
#define XWIN     (FPB * FP + 56)   // 856 samples: [t0-49, ...), padded for refills

typedef unsigned long long u64;

__device__ __forceinline__ void unpack2(u64 v, float& a, float& b) {
    asm("mov.b64 {%0, %1}, %2;" : "=f"(a), "=f"(b) : "l"(v));
}
__device__ __forceinline__ u64 ffma2(u64 a, u64 b, u64 c) {
    u64 d;
    asm("fma.rn.f32x2 %0, %1, %2, %3;" : "=l"(d) : "l"(a), "l"(b), "l"(c));
    return d;
}

__global__ __launch_bounds__(THREADS, 10)
void azdf_kernel(const float* __restrict__ x,
                 const float* __restrict__ b,
                 float* __restrict__ y,
                 int T, int Nf)
{
    __shared__ float2 sx2[XWIN];          // (v, v) duplicated samples, 6.85 KB
    __shared__ float2 sC[FPB * TAPS];     // (cL, cR-cL) interleaved, 4 KB

    const int bb = blockIdx.y;
    const int n0 = blockIdx.x * FPB;
    const int t0 = n0 * FP;

    const float* xb  = x + (long long)bb * T;
    const float* bbp = b + (long long)bb * Nf * TAPS;

    // ---- stage x window, duplicated ----
    for (int i = threadIdx.x; i < XWIN; i += THREADS) {
        int g = t0 - (TAPS - 1) + i;
        float v = (g >= 0 && g < T) ? xb[g] : 0.0f;
        sx2[i] = make_float2(v, v);
    }

    // ---- stage coefficients: flip + diff, interleaved ----
    for (int idx = threadIdx.x; idx < FPB * TAPS; idx += THREADS) {
        int r = idx / TAPS;
        int j = idx - r * TAPS;
        int n  = n0 + r;
        int n1 = min(n + 1, Nf - 1);
        float l  = bbp[n  * TAPS + (TAPS - 1 - j)];
        float rr = bbp[n1 * TAPS + (TAPS - 1 - j)];
        sC[idx] = make_float2(l, rr - l);
    }
    __syncthreads();

    // ---- per-thread: 5 consecutive outputs within one frame ----
    const int f  = threadIdx.x >> 4;      // frame within block (16 threads/frame)
    const int q  = threadIdx.x & 15;      // 5-output group within frame
    const int lt = 5 * threadIdx.x;       // == f*80 + q*5

    const u64* xd = (const u64*)sx2 + lt; // dup samples; stride-5 float2: conflict-free
    const ulonglong2* cp128 = (const ulonglong2*)(sC + f * TAPS); // f*400B: 16B-aligned

    u64 acc0 = 0, acc1 = 0, acc2 = 0, acc3 = 0, acc4 = 0;

    // 6-slot circular window: slot s holds dup x[lt + m] with m % 6 == s.
    u64 xw0 = xd[0], xw1 = xd[1], xw2 = xd[2], xw3 = xd[3], xw4 = xd[4], xw5 = xd[5];

    // Tap pair (J, J+1), J even. X0..X5 name slots (J%6)..(J%6+5) mod 6.
    // Tap J uses X0..X4; tap J+1 uses X1..X5. Then slots X0, X1 are refilled
    // with samples J+6, J+7 (one LDS.64 each, no packing).
#define TAPPAIR(J, X0, X1, X2, X3, X4, X5)             \
    {                                                  \
        ulonglong2 cc = cp128[(J) >> 1];               \
        acc0 = ffma2(X0, cc.x, acc0);                  \
        acc1 = ffma2(X1, cc.x, acc1);                  \
        acc2 = ffma2(X2, cc.x, acc2);                  \
        acc3 = ffma2(X3, cc.x, acc3);                  \
        acc4 = ffma2(X4, cc.x, acc4);                  \
        acc0 = ffma2(X1, cc.y, acc0);                  \
        acc1 = ffma2(X2, cc.y, acc1);                  \
        acc2 = ffma2(X3, cc.y, acc2);                  \
        acc3 = ffma2(X4, cc.y, acc3);                  \
        acc4 = ffma2(X5, cc.y, acc4);                  \
        X0 = xd[(J) + 6];                              \
        X1 = xd[(J) + 7];                              \
    }

    #pragma unroll
    for (int gg = 0; gg < 8; ++gg) {      // taps 0..47: 8 groups of 3 pairs (6 taps)
        const int j0 = 6 * gg;
        TAPPAIR(j0 + 0, xw0, xw1, xw2, xw3, xw4, xw5)
        TAPPAIR(j0 + 2, xw2, xw3, xw4, xw5, xw0, xw1)
        TAPPAIR(j0 + 4, xw4, xw5, xw0, xw1, xw2, xw3)
    }
    TAPPAIR(48, xw0, xw1, xw2, xw3, xw4, xw5)   // taps 48,49 (refill stays in-bounds)
#undef TAPPAIR

    // ---- interpolate + store ----
    const float p0 = (float)(q * KOUT);
    float* yp = y + (long long)bb * T + t0 + lt;
    float a0, a1;
    unpack2(acc0, a0, a1); yp[0] = fmaf((p0 + 0.0f) * (1.0f / FP), a1, a0);
    unpack2(acc1, a0, a1); yp[1] = fmaf((p0 + 1.0f) * (1.0f / FP), a1, a0);
    unpack2(acc2, a0, a1); yp[2] = fmaf((p0 + 2.0f) * (1.0f / FP), a1, a0);
    unpack2(acc3, a0, a1); yp[3] = fmaf((p0 + 3.0f) * (1.0f / FP), a1, a0);
    unpack2(acc4, a0, a1); yp[4] = fmaf((p0 + 4.0f) * (1.0f / FP), a1, a0);
}

extern "C" void kernel_launch(void* const* d_in, const int* in_sizes, int n_in,
                              void* d_out, int out_size)
{
    const float* x = (const float*)d_in[0];   // (B, T) float32
    const float* b = (const float*)d_in[1];   // (B, N, 50) float32
    float* y = (float*)d_out;                 // (B, T) float32

    const int Nf = 3000;
    const int T  = Nf * FP;                   // 240000
    const int B  = in_sizes[0] / T;           // 8

    dim3 grid(Nf / FPB, B);                   // (300, 8) = 2400 blocks
    azdf_kernel<<<grid, THREADS>>>(x, b, y, T, Nf);
}